// round 10
// baseline (speedup 1.0000x reference)
#include <cuda_runtime.h>
#include <cuda_fp16.h>
#include <stdint.h>

#define I_FEAT 4096
#define O_FEAT 11008
#define N_ROWS 4096

#define BM 64
#define BN 128
#define BK 32
#define SSTRIDE 40                  // halves per smem row (32 + 8 pad)
#define NKT (I_FEAT / BK)           // 128 k-tiles
#define NSTG 4                      // pipeline stages

// ---------------- scratch (allocation-free: device globals) ----------------
__device__ __half g_Wh[(size_t)O_FEAT * I_FEAT];   // dequantized W, fp16
__device__ __half g_Xh[(size_t)N_ROWS * I_FEAT];   // x, fp16

__device__ __forceinline__ uint32_t h2u(__half2 h) {
    union { __half2 h; uint32_t u; } c; c.h = h; return c.u;
}

// ---------------- x -> fp16 (16 elem/thread, MLP 4) ----------------
__global__ void tohalf_x_kernel(const float* __restrict__ x) {
    size_t base = ((size_t)blockIdx.x * blockDim.x + threadIdx.x) * 16;
    float4 v0 = *reinterpret_cast<const float4*>(x + base);
    float4 v1 = *reinterpret_cast<const float4*>(x + base + 4);
    float4 v2 = *reinterpret_cast<const float4*>(x + base + 8);
    float4 v3 = *reinterpret_cast<const float4*>(x + base + 12);
    uint4 o0, o1;
    o0.x = h2u(__floats2half2_rn(v0.x, v0.y));
    o0.y = h2u(__floats2half2_rn(v0.z, v0.w));
    o0.z = h2u(__floats2half2_rn(v1.x, v1.y));
    o0.w = h2u(__floats2half2_rn(v1.z, v1.w));
    o1.x = h2u(__floats2half2_rn(v2.x, v2.y));
    o1.y = h2u(__floats2half2_rn(v2.z, v2.w));
    o1.z = h2u(__floats2half2_rn(v3.x, v3.y));
    o1.w = h2u(__floats2half2_rn(v3.z, v3.w));
    *reinterpret_cast<uint4*>(g_Xh + base)     = o0;
    *reinterpret_cast<uint4*>(g_Xh + base + 8) = o1;
}

// ---------------- dequantize W -> fp16 (16 elem/thread, MLP 4) -------------
__global__ void dequant_kernel(const int* __restrict__ idx,
                               const float* __restrict__ scales,
                               const float* __restrict__ bab) {
    size_t base = ((size_t)blockIdx.x * blockDim.x + threadIdx.x) * 16;
    int4 q0 = *reinterpret_cast<const int4*>(idx + base);
    int4 q1 = *reinterpret_cast<const int4*>(idx + base + 4);
    int4 q2 = *reinterpret_cast<const int4*>(idx + base + 8);
    int4 q3 = *reinterpret_cast<const int4*>(idx + base + 12);
    size_t row = base >> 12;                 // / 4096
    int col = (int)(base & 4095);
    int blk = (int)(row << 4) + (col >> 8);  // 16 elems never cross a 256-block
    float s = scales[blk] * (1.0f / 127.0f);
    float b = bab[blk];
    uint4 o0, o1;
    o0.x = h2u(__floats2half2_rn((float)(q0.x - 128) * s + b, (float)(q0.y - 128) * s + b));
    o0.y = h2u(__floats2half2_rn((float)(q0.z - 128) * s + b, (float)(q0.w - 128) * s + b));
    o0.z = h2u(__floats2half2_rn((float)(q1.x - 128) * s + b, (float)(q1.y - 128) * s + b));
    o0.w = h2u(__floats2half2_rn((float)(q1.z - 128) * s + b, (float)(q1.w - 128) * s + b));
    o1.x = h2u(__floats2half2_rn((float)(q2.x - 128) * s + b, (float)(q2.y - 128) * s + b));
    o1.y = h2u(__floats2half2_rn((float)(q2.z - 128) * s + b, (float)(q2.w - 128) * s + b));
    o1.z = h2u(__floats2half2_rn((float)(q3.x - 128) * s + b, (float)(q3.y - 128) * s + b));
    o1.w = h2u(__floats2half2_rn((float)(q3.z - 128) * s + b, (float)(q3.w - 128) * s + b));
    *reinterpret_cast<uint4*>(g_Wh + base)     = o0;
    *reinterpret_cast<uint4*>(g_Wh + base + 8) = o1;
}

// ---------------- GEMM helpers ----------------
__device__ __forceinline__ void cp16(uint32_t dst, const void* src) {
    asm volatile("cp.async.cg.shared.global [%0], [%1], 16;\n" :: "r"(dst), "l"(src));
}
__device__ __forceinline__ void ldsm4(uint32_t& r0, uint32_t& r1, uint32_t& r2, uint32_t& r3,
                                      uint32_t addr) {
    asm volatile("ldmatrix.sync.aligned.m8n8.x4.shared.b16 {%0,%1,%2,%3}, [%4];\n"
        : "=r"(r0), "=r"(r1), "=r"(r2), "=r"(r3) : "r"(addr));
}
__device__ __forceinline__ void mma16816(float* c, const uint32_t* a, const uint32_t* b) {
    asm volatile("mma.sync.aligned.m16n8k16.row.col.f32.f16.f16.f32 "
        "{%0,%1,%2,%3}, {%4,%5,%6,%7}, {%8,%9}, {%0,%1,%2,%3};\n"
        : "+f"(c[0]), "+f"(c[1]), "+f"(c[2]), "+f"(c[3])
        : "r"(a[0]), "r"(a[1]), "r"(a[2]), "r"(a[3]), "r"(b[0]), "r"(b[1]));
}

// ---------------- fp16 GEMM, BM=64 tiles (finer wave quantization) ----------
__global__ void __launch_bounds__(256, 2)
gemm_kernel(const float* __restrict__ bias, float* __restrict__ out) {
    extern __shared__ __align__(16) __half sm[];
    const uint32_t smbase = (uint32_t)__cvta_generic_to_shared(sm);
    constexpr int TSZ_A = BM * SSTRIDE;          // 2560 halves
    constexpr int TSZ_B = BN * SSTRIDE;          // 5120 halves
    constexpr uint32_t STGB = (uint32_t)(TSZ_A + TSZ_B) * 2u;   // 15360 B

    const int m0 = (blockIdx.x & 63) * BM;       // m fastest -> W tiles shared via L2
    const int n0 = (blockIdx.x >> 6) * BN;
    const int tid = threadIdx.x;
    const int lane = tid & 31;
    const int wm = ((tid >> 5) & 1) * 32;        // 2 warps in m, warp tile 32x32
    const int wn = (tid >> 6) * 32;              // 4 warps in n

    // ---- cp.async descriptors: 3 x 16B per thread per stage ----
    const int rowa = tid >> 2;                   // 0..63
    const int ch = tid & 3;
    const __half* pA = g_Xh + (size_t)(m0 + rowa) * I_FEAT + ch * 8;
    const __half* pB = g_Wh + (size_t)(n0 + rowa) * I_FEAT + ch * 8;
    const uint32_t dA = (uint32_t)(rowa * SSTRIDE + ch * 8) * 2;
    const uint32_t dB = (uint32_t)(TSZ_A + rowa * SSTRIDE + ch * 8) * 2;
    constexpr size_t RSTEP = (size_t)64 * I_FEAT;
    constexpr uint32_t DSTEP = (uint32_t)(64 * SSTRIDE) * 2;

    auto load_stage = [&](int stg, int kt) {
        const uint32_t sb = smbase + (uint32_t)stg * STGB;
        const __half* a = pA + (size_t)kt * BK;
        const __half* b = pB + (size_t)kt * BK;
        cp16(sb + dA, a);
        cp16(sb + dB, b);
        cp16(sb + dB + DSTEP, b + RSTEP);
    };

    // ---- hoisted ldsm offsets (relative to stage base) ----
    uint32_t offB[2][2], offA[2][2];   // [ks][j], [ks][mi]
#pragma unroll
    for (int ks = 0; ks < 2; ++ks) {
#pragma unroll
        for (int j = 0; j < 2; ++j) {
            int brow = wn + j * 16 + (lane & 7) + ((lane >> 4) << 3);
            int bcol = ks * 16 + ((lane >> 3) & 1) * 8;
            offB[ks][j] = (uint32_t)(TSZ_A + brow * SSTRIDE + bcol) * 2;
        }
#pragma unroll
        for (int mi = 0; mi < 2; ++mi) {
            int arow = wm + mi * 16 + (lane & 15);
            int acol = ks * 16 + ((lane >> 4) << 3);
            offA[ks][mi] = (uint32_t)(arow * SSTRIDE + acol) * 2;
        }
    }

    float acc[2][4][4];
#pragma unroll
    for (int i = 0; i < 2; ++i)
#pragma unroll
        for (int j = 0; j < 4; ++j)
#pragma unroll
            for (int k = 0; k < 4; ++k) acc[i][j][k] = 0.0f;

    // prologue: stages 0..2 <- k-tiles 0..2
#pragma unroll
    for (int s = 0; s < NSTG - 1; ++s) {
        load_stage(s, s);
        asm volatile("cp.async.commit_group;\n");
    }

#pragma unroll 4
    for (int kt = 0; kt < NKT; ++kt) {
        asm volatile("cp.async.wait_group %0;\n" :: "n"(NSTG - 2));
        __syncthreads();   // stage kt visible; all warps done reading stage kt-1

        const uint32_t sbase = smbase + (uint32_t)(kt & (NSTG - 1)) * STGB;

        // ---- ks = 0 ----
        {
            uint32_t B[4][2];
            ldsm4(B[0][0], B[0][1], B[1][0], B[1][1], sbase + offB[0][0]);
            ldsm4(B[2][0], B[2][1], B[3][0], B[3][1], sbase + offB[0][1]);
#pragma unroll
            for (int mi = 0; mi < 2; ++mi) {
                uint32_t a[4];
                ldsm4(a[0], a[1], a[2], a[3], sbase + offA[0][mi]);
#pragma unroll
                for (int ni = 0; ni < 4; ++ni)
                    mma16816(acc[mi][ni], a, B[ni]);
            }
        }

        // ---- prefetch stage kt+3 (overwrites buffer kt-1: safe post-barrier) ----
        if (kt + NSTG - 1 < NKT)
            load_stage((kt + NSTG - 1) & (NSTG - 1), kt + NSTG - 1);
        asm volatile("cp.async.commit_group;\n");

        // ---- ks = 1 ----
        {
            uint32_t B[4][2];
            ldsm4(B[0][0], B[0][1], B[1][0], B[1][1], sbase + offB[1][0]);
            ldsm4(B[2][0], B[2][1], B[3][0], B[3][1], sbase + offB[1][1]);
#pragma unroll
            for (int mi = 0; mi < 2; ++mi) {
                uint32_t a[4];
                ldsm4(a[0], a[1], a[2], a[3], sbase + offA[1][mi]);
#pragma unroll
                for (int ni = 0; ni < 4; ++ni)
                    mma16816(acc[mi][ni], a, B[ni]);
            }
        }
    }

    // ---- epilogue: add bias, store fp32 ----
    const int g = lane >> 2;
    const int t4 = lane & 3;
    float2 bb[4];
#pragma unroll
    for (int ni = 0; ni < 4; ++ni) {
        int col = n0 + wn + ni * 8 + t4 * 2;
        bb[ni].x = __ldg(bias + col);
        bb[ni].y = __ldg(bias + col + 1);
    }
#pragma unroll
    for (int mi = 0; mi < 2; ++mi) {
        int row0 = m0 + wm + mi * 16 + g;
#pragma unroll
        for (int ni = 0; ni < 4; ++ni) {
            int col = n0 + wn + ni * 8 + t4 * 2;
            float2 v0 = { acc[mi][ni][0] + bb[ni].x, acc[mi][ni][1] + bb[ni].y };
            float2 v1 = { acc[mi][ni][2] + bb[ni].x, acc[mi][ni][3] + bb[ni].y };
            *reinterpret_cast<float2*>(out + (size_t)row0 * O_FEAT + col) = v0;
            *reinterpret_cast<float2*>(out + (size_t)(row0 + 8) * O_FEAT + col) = v1;
        }
    }
}

// ---------------- launch ----------------
extern "C" void kernel_launch(void* const* d_in, const int* in_sizes, int n_in,
                              void* d_out, int out_size) {
    const float* x    = (const float*)d_in[0];
    const int*   idx  = (const int*)d_in[1];
    const float* sc   = (const float*)d_in[2];
    const float* bab  = (const float*)d_in[3];
    const float* bias = (const float*)d_in[4];
    float* out = (float*)d_out;

    tohalf_x_kernel<<<(int)(((size_t)N_ROWS * I_FEAT) / (256 * 16)), 256>>>(x);
    dequant_kernel<<<(int)(((size_t)O_FEAT * I_FEAT) / (256 * 16)), 256>>>(idx, sc, bab);

    const int smem_bytes = NSTG * (BM + BN) * SSTRIDE * 2;   // 61440
    cudaFuncSetAttribute(gemm_kernel, cudaFuncAttributeMaxDynamicSharedMemorySize, smem_bytes);
    gemm_kernel<<<(N_ROWS / BM) * (O_FEAT / BN), 256, smem_bytes>>>(bias, out);
}

// round 11
// speedup vs baseline: 1.2922x; 1.2922x over previous
#include <cuda_runtime.h>
#include <cuda_fp16.h>
#include <stdint.h>

#define I_FEAT 4096
#define O_FEAT 11008
#define N_ROWS 4096

#define BM 128
#define BN 128
#define BK 32
#define SSTRIDE 40                  // halves per smem row (32 + 8 pad)
#define NKT (I_FEAT / BK)           // 128 k-tiles
#define NSTG 4                      // pipeline stages

#define GX_BLOCKS ((int)(((size_t)N_ROWS * I_FEAT) / (256 * 8)))   // 8192
#define GW_BLOCKS ((int)(((size_t)O_FEAT * I_FEAT) / (256 * 8)))   // 22016

// ---------------- scratch (allocation-free: device globals) ----------------
__device__ __half g_Wh[(size_t)O_FEAT * I_FEAT];   // dequantized W, fp16
__device__ __half g_Xh[(size_t)N_ROWS * I_FEAT];   // x, fp16

__device__ __forceinline__ uint32_t h2u(__half2 h) {
    union { __half2 h; uint32_t u; } c; c.h = h; return c.u;
}

// ---------------- merged prep: x->fp16 and W dequant in one launch ----------
__global__ void prep_kernel(const float* __restrict__ x,
                            const int* __restrict__ idx,
                            const float* __restrict__ scales,
                            const float* __restrict__ bab) {
    if (blockIdx.x < GX_BLOCKS) {
        size_t base = ((size_t)blockIdx.x * blockDim.x + threadIdx.x) * 8;
        float4 v0 = *reinterpret_cast<const float4*>(x + base);
        float4 v1 = *reinterpret_cast<const float4*>(x + base + 4);
        uint4 o;
        o.x = h2u(__floats2half2_rn(v0.x, v0.y));
        o.y = h2u(__floats2half2_rn(v0.z, v0.w));
        o.z = h2u(__floats2half2_rn(v1.x, v1.y));
        o.w = h2u(__floats2half2_rn(v1.z, v1.w));
        *reinterpret_cast<uint4*>(g_Xh + base) = o;
    } else {
        size_t base = ((size_t)(blockIdx.x - GX_BLOCKS) * blockDim.x + threadIdx.x) * 8;
        int4 q0 = *reinterpret_cast<const int4*>(idx + base);
        int4 q1 = *reinterpret_cast<const int4*>(idx + base + 4);
        size_t row = base >> 12;                 // / 4096
        int col = (int)(base & 4095);
        int blk = (int)(row << 4) + (col >> 8);  // 8 elems never cross a 256-block
        float s = scales[blk] * (1.0f / 127.0f);
        float b = bab[blk];
        float w0 = (float)(q0.x - 128) * s + b;
        float w1 = (float)(q0.y - 128) * s + b;
        float w2 = (float)(q0.z - 128) * s + b;
        float w3 = (float)(q0.w - 128) * s + b;
        float w4 = (float)(q1.x - 128) * s + b;
        float w5 = (float)(q1.y - 128) * s + b;
        float w6 = (float)(q1.z - 128) * s + b;
        float w7 = (float)(q1.w - 128) * s + b;
        uint4 o;
        o.x = h2u(__floats2half2_rn(w0, w1));
        o.y = h2u(__floats2half2_rn(w2, w3));
        o.z = h2u(__floats2half2_rn(w4, w5));
        o.w = h2u(__floats2half2_rn(w6, w7));
        *reinterpret_cast<uint4*>(g_Wh + base) = o;
    }
}

// ---------------- GEMM helpers ----------------
__device__ __forceinline__ void cp16(uint32_t dst, const void* src) {
    asm volatile("cp.async.cg.shared.global [%0], [%1], 16;\n" :: "r"(dst), "l"(src));
}
__device__ __forceinline__ void ldsm4(uint32_t& r0, uint32_t& r1, uint32_t& r2, uint32_t& r3,
                                      uint32_t addr) {
    asm volatile("ldmatrix.sync.aligned.m8n8.x4.shared.b16 {%0,%1,%2,%3}, [%4];\n"
        : "=r"(r0), "=r"(r1), "=r"(r2), "=r"(r3) : "r"(addr));
}
__device__ __forceinline__ void mma16816(float* c, const uint32_t* a, const uint32_t* b) {
    asm volatile("mma.sync.aligned.m16n8k16.row.col.f32.f16.f16.f32 "
        "{%0,%1,%2,%3}, {%4,%5,%6,%7}, {%8,%9}, {%0,%1,%2,%3};\n"
        : "+f"(c[0]), "+f"(c[1]), "+f"(c[2]), "+f"(c[3])
        : "r"(a[0]), "r"(a[1]), "r"(a[2]), "r"(a[3]), "r"(b[0]), "r"(b[1]));
}

// ---------------- single fp16 GEMM, 4-stage, one barrier/iter ----------------
__global__ void __launch_bounds__(256, 2)
gemm_kernel(const float* __restrict__ bias, float* __restrict__ out) {
    extern __shared__ __align__(16) __half sm[];
    const uint32_t smbase = (uint32_t)__cvta_generic_to_shared(sm);
    constexpr int TSZ = BM * SSTRIDE;            // 5120 halves per tile
    constexpr uint32_t STGB = 2u * TSZ * 2u;     // stage bytes (A+B)

    const int m0 = (blockIdx.x & 31) * BM;       // m fastest -> W tiles shared via L2
    const int n0 = (blockIdx.x >> 5) * BN;
    const int tid = threadIdx.x;
    const int lane = tid & 31;
    const int wm = ((tid >> 5) & 1) * 64;        // 2 warps in m
    const int wn = (tid >> 6) * 32;              // 4 warps in n, warp tile 64x32

    // ---- cp.async descriptors: 4 x 16B per thread per stage ----
    const int rowa = tid >> 2;
    const int ch = tid & 3;
    const __half* pA = g_Xh + (size_t)(m0 + rowa) * I_FEAT + ch * 8;
    const __half* pB = g_Wh + (size_t)(n0 + rowa) * I_FEAT + ch * 8;
    const uint32_t dA = (uint32_t)(rowa * SSTRIDE + ch * 8) * 2;
    const uint32_t dB = (uint32_t)(TSZ + rowa * SSTRIDE + ch * 8) * 2;
    constexpr size_t RSTEP = (size_t)64 * I_FEAT;
    constexpr uint32_t DSTEP = (uint32_t)(64 * SSTRIDE) * 2;

    auto load_stage = [&](int stg, int kt) {
        const uint32_t sb = smbase + (uint32_t)stg * STGB;
        const __half* a = pA + (size_t)kt * BK;
        const __half* b = pB + (size_t)kt * BK;
        cp16(sb + dA, a);
        cp16(sb + dA + DSTEP, a + RSTEP);
        cp16(sb + dB, b);
        cp16(sb + dB + DSTEP, b + RSTEP);
    };

    // ---- hoisted ldsm offsets (relative to stage base) ----
    uint32_t offB[2][2], offA[2][4];   // [ks][j], [ks][mi]
#pragma unroll
    for (int ks = 0; ks < 2; ++ks) {
#pragma unroll
        for (int j = 0; j < 2; ++j) {
            int brow = wn + j * 16 + (lane & 7) + ((lane >> 4) << 3);
            int bcol = ks * 16 + ((lane >> 3) & 1) * 8;
            offB[ks][j] = (uint32_t)(TSZ + brow * SSTRIDE + bcol) * 2;
        }
#pragma unroll
        for (int mi = 0; mi < 4; ++mi) {
            int arow = wm + mi * 16 + (lane & 15);
            int acol = ks * 16 + ((lane >> 4) << 3);
            offA[ks][mi] = (uint32_t)(arow * SSTRIDE + acol) * 2;
        }
    }

    float acc[4][4][4];
#pragma unroll
    for (int i = 0; i < 4; ++i)
#pragma unroll
        for (int j = 0; j < 4; ++j)
#pragma unroll
            for (int k = 0; k < 4; ++k) acc[i][j][k] = 0.0f;

    // prologue: stages 0..2 <- k-tiles 0..2
#pragma unroll
    for (int s = 0; s < NSTG - 1; ++s) {
        load_stage(s, s);
        asm volatile("cp.async.commit_group;\n");
    }

#pragma unroll 4
    for (int kt = 0; kt < NKT; ++kt) {
        asm volatile("cp.async.wait_group %0;\n" :: "n"(NSTG - 2));
        __syncthreads();   // stage kt visible; all warps done reading stage kt-1

        const uint32_t sbase = smbase + (uint32_t)(kt & (NSTG - 1)) * STGB;

        // ---- ks = 0 ----
        {
            uint32_t B[4][2];
            ldsm4(B[0][0], B[0][1], B[1][0], B[1][1], sbase + offB[0][0]);
            ldsm4(B[2][0], B[2][1], B[3][0], B[3][1], sbase + offB[0][1]);
#pragma unroll
            for (int mi = 0; mi < 4; ++mi) {
                uint32_t a[4];
                ldsm4(a[0], a[1], a[2], a[3], sbase + offA[0][mi]);
#pragma unroll
                for (int ni = 0; ni < 4; ++ni)
                    mma16816(acc[mi][ni], a, B[ni]);
            }
        }

        // ---- prefetch stage kt+3 (overwrites buffer kt-1: safe post-barrier) ----
        if (kt + NSTG - 1 < NKT)
            load_stage((kt + NSTG - 1) & (NSTG - 1), kt + NSTG - 1);
        asm volatile("cp.async.commit_group;\n");

        // ---- ks = 1 ----
        {
            uint32_t B[4][2];
            ldsm4(B[0][0], B[0][1], B[1][0], B[1][1], sbase + offB[1][0]);
            ldsm4(B[2][0], B[2][1], B[3][0], B[3][1], sbase + offB[1][1]);
#pragma unroll
            for (int mi = 0; mi < 4; ++mi) {
                uint32_t a[4];
                ldsm4(a[0], a[1], a[2], a[3], sbase + offA[1][mi]);
#pragma unroll
                for (int ni = 0; ni < 4; ++ni)
                    mma16816(acc[mi][ni], a, B[ni]);
            }
        }
    }

    // ---- epilogue: add bias, store fp32 ----
    const int g = lane >> 2;
    const int t4 = lane & 3;
    float2 bb[4];
#pragma unroll
    for (int ni = 0; ni < 4; ++ni) {
        int col = n0 + wn + ni * 8 + t4 * 2;
        bb[ni].x = __ldg(bias + col);
        bb[ni].y = __ldg(bias + col + 1);
    }
#pragma unroll
    for (int mi = 0; mi < 4; ++mi) {
        int row0 = m0 + wm + mi * 16 + g;
#pragma unroll
        for (int ni = 0; ni < 4; ++ni) {
            int col = n0 + wn + ni * 8 + t4 * 2;
            float2 v0 = { acc[mi][ni][0] + bb[ni].x, acc[mi][ni][1] + bb[ni].y };
            float2 v1 = { acc[mi][ni][2] + bb[ni].x, acc[mi][ni][3] + bb[ni].y };
            *reinterpret_cast<float2*>(out + (size_t)row0 * O_FEAT + col) = v0;
            *reinterpret_cast<float2*>(out + (size_t)(row0 + 8) * O_FEAT + col) = v1;
        }
    }
}

// ---------------- launch ----------------
extern "C" void kernel_launch(void* const* d_in, const int* in_sizes, int n_in,
                              void* d_out, int out_size) {
    const float* x    = (const float*)d_in[0];
    const int*   idx  = (const int*)d_in[1];
    const float* sc   = (const float*)d_in[2];
    const float* bab  = (const float*)d_in[3];
    const float* bias = (const float*)d_in[4];
    float* out = (float*)d_out;

    prep_kernel<<<GX_BLOCKS + GW_BLOCKS, 256>>>(x, idx, sc, bab);

    const int smem_bytes = NSTG * 2 * BM * SSTRIDE * 2;   // 81920
    cudaFuncSetAttribute(gemm_kernel, cudaFuncAttributeMaxDynamicSharedMemorySize, smem_bytes);
    gemm_kernel<<<(N_ROWS / BM) * (O_FEAT / BN), 256, smem_bytes>>>(bias, out);
}